// round 2
// baseline (speedup 1.0000x reference)
#include <cuda_runtime.h>
#include <cuda_bf16.h>
#include <math.h>

// Problem constants
#define NN 30000      // nodes
#define EE 150000     // edges per graph
#define IND 512
#define HIDD 512
#define OUTD 256
#define GG 3
#define CONCAT (HIDD * GG)   // 1536

// ---------------------------------------------------------------------------
// Scratch (device globals; no dynamic allocation allowed)
// ---------------------------------------------------------------------------
__device__ float g_Y[(size_t)NN * CONCAT];   // X @ [W0|W1|W2], row-scaled by rsqrt(deg_out_g)
__device__ float g_H[(size_t)NN * CONCAT];   // tanh(a_g*(agg*rsqrt(deg_in)+b_g))
__device__ int   g_deg_in [GG * NN];
__device__ int   g_deg_out[GG * NN];
__device__ int   g_off    [GG * (NN + 1)];
__device__ int   g_cursor [GG * NN];
__device__ int   g_csr_src[GG * EE];
__device__ float g_alpha  [GG];

// ---------------------------------------------------------------------------
// Setup: zero degree arrays + softmax(alphas)
// ---------------------------------------------------------------------------
__global__ void zero_kernel(const float* __restrict__ alphas) {
    int i = blockIdx.x * blockDim.x + threadIdx.x;
    int total = 2 * GG * NN;
    for (int idx = i; idx < total; idx += gridDim.x * blockDim.x) {
        if (idx < GG * NN) g_deg_in[idx] = 0;
        else               g_deg_out[idx - GG * NN] = 0;
    }
    if (blockIdx.x == 0 && threadIdx.x == 0) {
        float m = alphas[0];
        for (int g = 1; g < GG; g++) m = fmaxf(m, alphas[g]);
        float s = 0.f, e[GG];
        for (int g = 0; g < GG; g++) { e[g] = expf(alphas[g] - m); s += e[g]; }
        for (int g = 0; g < GG; g++) g_alpha[g] = e[g] / s;
    }
}

// ---------------------------------------------------------------------------
// Degree histogram over all 3 edge lists
// ---------------------------------------------------------------------------
__global__ void hist_kernel(const int* __restrict__ e0,
                            const int* __restrict__ e1,
                            const int* __restrict__ e2) {
    int i = blockIdx.x * blockDim.x + threadIdx.x;
    if (i >= GG * EE) return;
    int g = i / EE, idx = i - g * EE;
    const int* e = (g == 0) ? e0 : (g == 1) ? e1 : e2;
    int src = e[idx];
    int dst = e[EE + idx];
    atomicAdd(&g_deg_out[g * NN + src], 1);
    atomicAdd(&g_deg_in [g * NN + dst], 1);
}

// ---------------------------------------------------------------------------
// Exclusive scan of deg_in -> CSR offsets (one block per graph)
// ---------------------------------------------------------------------------
__global__ void scan_kernel() {
    int g = blockIdx.x;
    const int* cnt = g_deg_in + g * NN;
    int* off = g_off + g * (NN + 1);
    int* cur = g_cursor + g * NN;
    __shared__ int sh[1024];
    int carry = 0;
    for (int base = 0; base < NN; base += 1024) {
        int i = base + threadIdx.x;
        int v = (i < NN) ? cnt[i] : 0;
        sh[threadIdx.x] = v;
        __syncthreads();
        #pragma unroll
        for (int s = 1; s < 1024; s <<= 1) {
            int t = (threadIdx.x >= s) ? sh[threadIdx.x - s] : 0;
            __syncthreads();
            sh[threadIdx.x] += t;
            __syncthreads();
        }
        int incl = sh[threadIdx.x];
        if (i < NN) {
            int excl = carry + incl - v;
            off[i] = excl;
            cur[i] = excl;
        }
        carry += sh[1023];
        __syncthreads();
    }
    if (threadIdx.x == 0) off[NN] = carry;
}

// ---------------------------------------------------------------------------
// Fill CSR src lists
// ---------------------------------------------------------------------------
__global__ void fill_kernel(const int* __restrict__ e0,
                            const int* __restrict__ e1,
                            const int* __restrict__ e2) {
    int i = blockIdx.x * blockDim.x + threadIdx.x;
    if (i >= GG * EE) return;
    int g = i / EE, idx = i - g * EE;
    const int* e = (g == 0) ? e0 : (g == 1) ? e1 : e2;
    int src = e[idx];
    int dst = e[EE + idx];
    int p = atomicAdd(&g_cursor[g * NN + dst], 1);
    g_csr_src[g * EE + p] = src;
}

// ---------------------------------------------------------------------------
// Register-blocked SGEMM, 128x64 tile, BK=16, 8x4 per thread, 256 threads.
// mode 1: C = g_Y + g*HIDD (ldc=CONCAT), row-scaled by rsqrt(max(deg_out_g,1))
// mode 2: C = Cext (out), bias added
// ---------------------------------------------------------------------------
#define GBM 128
#define GBN 64
#define GBK 16

__global__ void __launch_bounds__(256)
sgemm_kernel(const float* __restrict__ Aext, const float* __restrict__ B,
             float* Cext, int lda, int ldb, int ldc, int M, int K,
             const float* __restrict__ bias, int mode, int g) {
    __shared__ float As[GBK][GBM + 4];
    __shared__ float Bs[GBK][GBN];

    const float* A = Aext ? Aext : g_H;
    float* C;
    const int* rdeg = nullptr;
    if (mode == 1) { C = g_Y + g * HIDD; rdeg = g_deg_out + g * NN; }
    else           { C = Cext; }

    int tid = threadIdx.x;
    int tx = tid & 15;        // N dir
    int ty = tid >> 4;        // M dir
    int row0 = blockIdx.x * GBM;
    int col0 = blockIdx.y * GBN;

    // A-load mapping: rows r0 and r0+64, 4 k's at kq
    int r0 = tid >> 2;
    int kq = (tid & 3) << 2;
    int row_a0 = row0 + r0;
    int row_a1 = row0 + r0 + 64;
    bool va0 = row_a0 < M;
    bool va1 = row_a1 < M;
    const float* Ap0 = A + (size_t)row_a0 * lda + kq;
    const float* Ap1 = A + (size_t)row_a1 * lda + kq;
    // B-load mapping: row kb, 4 cols at nq
    int kb = tid >> 4;
    int nq = (tid & 15) << 2;
    const float* Bp = B + (size_t)kb * ldb + col0 + nq;

    float4 z4 = make_float4(0.f, 0.f, 0.f, 0.f);
    float4 fa0 = va0 ? *(const float4*)Ap0 : z4;
    float4 fa1 = va1 ? *(const float4*)Ap1 : z4;
    float4 fb  = *(const float4*)Bp;

    float acc[8][4];
    #pragma unroll
    for (int i = 0; i < 8; i++)
        #pragma unroll
        for (int j = 0; j < 4; j++) acc[i][j] = 0.f;

    for (int kt = 0; kt < K; kt += GBK) {
        // store current tile to smem
        As[kq + 0][r0] = fa0.x; As[kq + 1][r0] = fa0.y;
        As[kq + 2][r0] = fa0.z; As[kq + 3][r0] = fa0.w;
        As[kq + 0][r0 + 64] = fa1.x; As[kq + 1][r0 + 64] = fa1.y;
        As[kq + 2][r0 + 64] = fa1.z; As[kq + 3][r0 + 64] = fa1.w;
        *(float4*)&Bs[kb][nq] = fb;
        __syncthreads();

        // prefetch next tile (in flight during compute)
        if (kt + GBK < K) {
            int ko = kt + GBK;
            fa0 = va0 ? *(const float4*)(Ap0 + ko) : z4;
            fa1 = va1 ? *(const float4*)(Ap1 + ko) : z4;
            fb  = *(const float4*)(Bp + (size_t)ko * ldb);
        }

        #pragma unroll
        for (int k = 0; k < GBK; k++) {
            float4 a0 = *(const float4*)&As[k][ty * 8];
            float4 a1 = *(const float4*)&As[k][ty * 8 + 4];
            float4 bv = *(const float4*)&Bs[k][tx * 4];
            float av[8] = {a0.x, a0.y, a0.z, a0.w, a1.x, a1.y, a1.z, a1.w};
            float bw[4] = {bv.x, bv.y, bv.z, bv.w};
            #pragma unroll
            for (int i = 0; i < 8; i++)
                #pragma unroll
                for (int j = 0; j < 4; j++)
                    acc[i][j] = fmaf(av[i], bw[j], acc[i][j]);
        }
        __syncthreads();
    }

    int crow = row0 + ty * 8;
    int ccol = col0 + tx * 4;
    #pragma unroll
    for (int i = 0; i < 8; i++) {
        int grow = crow + i;
        if (grow >= M) break;
        float scale = 1.0f;
        if (rdeg) {
            int d = rdeg[grow];
            scale = rsqrtf((float)(d > 1 ? d : 1));
        }
        float4 o = make_float4(acc[i][0] * scale, acc[i][1] * scale,
                               acc[i][2] * scale, acc[i][3] * scale);
        if (bias) {
            o.x += bias[ccol + 0]; o.y += bias[ccol + 1];
            o.z += bias[ccol + 2]; o.w += bias[ccol + 3];
        }
        *(float4*)&C[(size_t)grow * ldc + ccol] = o;
    }
}

// ---------------------------------------------------------------------------
// CSR aggregation + rsqrt(deg_in) + bias + alpha + tanh, fused.
// grid = (NN, GG), 128 threads; each thread owns 4 consecutive columns.
// ---------------------------------------------------------------------------
__global__ void __launch_bounds__(128)
agg_kernel(const float* __restrict__ b0, const float* __restrict__ b1,
           const float* __restrict__ b2) {
    int dst = blockIdx.x;
    int g = blockIdx.y;
    int c = threadIdx.x * 4;

    int beg = g_off[g * (NN + 1) + dst];
    int end = g_off[g * (NN + 1) + dst + 1];
    const int* srcs = g_csr_src + g * EE;
    const float* Ybase = g_Y + (size_t)g * HIDD + c;

    float4 acc = make_float4(0.f, 0.f, 0.f, 0.f);
    for (int e = beg; e < end; e++) {
        int s = srcs[e];
        float4 v = *(const float4*)(Ybase + (size_t)s * CONCAT);
        acc.x += v.x; acc.y += v.y; acc.z += v.z; acc.w += v.w;
    }

    int d = g_deg_in[g * NN + dst];
    float rsv = rsqrtf((float)(d > 1 ? d : 1));
    const float* bb = (g == 0) ? b0 : (g == 1) ? b1 : b2;
    float4 bv = *(const float4*)(bb + c);
    float a = g_alpha[g];

    float4 o;
    o.x = tanhf(a * (acc.x * rsv + bv.x));
    o.y = tanhf(a * (acc.y * rsv + bv.y));
    o.z = tanhf(a * (acc.z * rsv + bv.z));
    o.w = tanhf(a * (acc.w * rsv + bv.w));
    *(float4*)(g_H + (size_t)dst * CONCAT + (size_t)g * HIDD + c) = o;
}

// ---------------------------------------------------------------------------
// Launch — inputs bound by element count (robust to metadata ordering).
// Classes: x=NN*IND, edges=2*EE, W=IND*HIDD, b=HIDD, alphas=GG,
//          W_lin=CONCAT*OUTD, b_lin=OUTD. Encounter order preserved per class.
// ---------------------------------------------------------------------------
extern "C" void kernel_launch(void* const* d_in, const int* in_sizes, int n_in,
                              void* d_out, int out_size) {
    const float* x = nullptr;
    const int*   e[GG]  = {nullptr, nullptr, nullptr};
    const float* W[GG]  = {nullptr, nullptr, nullptr};
    const float* b[GG]  = {nullptr, nullptr, nullptr};
    const float* alphas = nullptr;
    const float* W_lin  = nullptr;
    const float* b_lin  = nullptr;
    int ne = 0, nw = 0, nb = 0;

    for (int i = 0; i < n_in; i++) {
        int sz = in_sizes[i];
        if      (sz == NN * IND)        x = (const float*)d_in[i];
        else if (sz == 2 * EE)          { if (ne < GG) e[ne++] = (const int*)d_in[i]; }
        else if (sz == IND * HIDD)      { if (nw < GG) W[nw++] = (const float*)d_in[i]; }
        else if (sz == HIDD)            { if (nb < GG) b[nb++] = (const float*)d_in[i]; }
        else if (sz == GG)              alphas = (const float*)d_in[i];
        else if (sz == CONCAT * OUTD)   W_lin = (const float*)d_in[i];
        else if (sz == OUTD)            b_lin = (const float*)d_in[i];
    }
    float* out = (float*)d_out;

    zero_kernel<<<256, 256>>>(alphas);
    hist_kernel<<<(GG * EE + 255) / 256, 256>>>(e[0], e[1], e[2]);
    scan_kernel<<<GG, 1024>>>();
    fill_kernel<<<(GG * EE + 255) / 256, 256>>>(e[0], e[1], e[2]);

    // GEMM1 per branch: Y[:, g*512:(g+1)*512] = X @ W_g, rows scaled rsqrt(deg_out_g)
    dim3 grid1((NN + GBM - 1) / GBM, HIDD / GBN);
    sgemm_kernel<<<grid1, 256>>>(x, W[0], nullptr, IND, HIDD, CONCAT, NN, IND, nullptr, 1, 0);
    sgemm_kernel<<<grid1, 256>>>(x, W[1], nullptr, IND, HIDD, CONCAT, NN, IND, nullptr, 1, 1);
    sgemm_kernel<<<grid1, 256>>>(x, W[2], nullptr, IND, HIDD, CONCAT, NN, IND, nullptr, 1, 2);

    // CSR aggregation + epilogue (scale, bias, alpha, tanh) -> H
    dim3 gridA(NN, GG);
    agg_kernel<<<gridA, 128>>>(b[0], b[1], b[2]);

    // GEMM2: out = H @ W_lin + b_lin
    dim3 grid2((NN + GBM - 1) / GBM, OUTD / GBN);
    sgemm_kernel<<<grid2, 256>>>(nullptr, W_lin, out, CONCAT, OUTD, OUTD, NN, CONCAT, b_lin, 2, 0);
}

// round 4
// speedup vs baseline: 1.7063x; 1.7063x over previous
#include <cuda_runtime.h>
#include <cuda_bf16.h>
#include <math.h>
#include <stdint.h>

// Problem constants
#define NN 30000      // nodes
#define EE 150000     // edges per graph
#define IND 512
#define HIDD 512
#define OUTD 256
#define GG 3
#define CONCAT (HIDD * GG)   // 1536

// ============================================================================
// Scratch (device globals)
// ============================================================================
__device__ float g_Y[(size_t)NN * CONCAT];          // GEMM1 output (deg_out-scaled), f32
__device__ __nv_bfloat16 g_Xhi[(size_t)NN * IND];
__device__ __nv_bfloat16 g_Xlo[(size_t)NN * IND];
__device__ __nv_bfloat16 g_Hhi[(size_t)NN * CONCAT];
__device__ __nv_bfloat16 g_Hlo[(size_t)NN * CONCAT];
__device__ __nv_bfloat16 g_Bthi[(size_t)CONCAT * IND];   // [W0|W1|W2]^T : row n, col k
__device__ __nv_bfloat16 g_Btlo[(size_t)CONCAT * IND];
__device__ __nv_bfloat16 g_BtLhi[(size_t)OUTD * CONCAT]; // W_lin^T : row n, col k
__device__ __nv_bfloat16 g_BtLlo[(size_t)OUTD * CONCAT];
__device__ int   g_deg_in [GG * NN];
__device__ int   g_deg_out[GG * NN];
__device__ int   g_off    [GG * (NN + 1)];
__device__ int   g_cursor [GG * NN];
__device__ int   g_csr_src[GG * EE];
__device__ float g_alpha  [GG];

// ============================================================================
// PTX helpers (all plain-sm_103-legal: cp.async / ldmatrix / mma.sync)
// ============================================================================
__device__ __forceinline__ uint32_t smem_to_u32(const void* p) {
    uint32_t a;
    asm("{ .reg .u64 t; cvta.to.shared.u64 t, %1; cvt.u32.u64 %0, t; }" : "=r"(a) : "l"(p));
    return a;
}
#define CP16(dst32, src) \
    asm volatile("cp.async.cg.shared.global [%0], [%1], 16;" :: "r"(dst32), "l"(src))
#define CP_COMMIT() asm volatile("cp.async.commit_group;" ::: "memory")
#define CP_WAIT(n)  asm volatile("cp.async.wait_group %0;" :: "n"(n) : "memory")

#define LDSM_X4(r0, r1, r2, r3, addr) \
    asm volatile("ldmatrix.sync.aligned.m8n8.x4.shared.b16 {%0,%1,%2,%3}, [%4];" \
        : "=r"(r0), "=r"(r1), "=r"(r2), "=r"(r3) : "r"(addr))

#define MMA_BF16(c, a, b) \
    asm volatile("mma.sync.aligned.m16n8k16.row.col.f32.bf16.bf16.f32 " \
        "{%0,%1,%2,%3}, {%4,%5,%6,%7}, {%8,%9}, {%0,%1,%2,%3};" \
        : "+f"((c)[0]), "+f"((c)[1]), "+f"((c)[2]), "+f"((c)[3]) \
        : "r"((a)[0]), "r"((a)[1]), "r"((a)[2]), "r"((a)[3]), "r"((b)[0]), "r"((b)[1]))

// ============================================================================
// Setup kernels
// ============================================================================
__global__ void zero_kernel(const float* __restrict__ alphas) {
    int i = blockIdx.x * blockDim.x + threadIdx.x;
    int total = 2 * GG * NN;
    for (int idx = i; idx < total; idx += gridDim.x * blockDim.x) {
        if (idx < GG * NN) g_deg_in[idx] = 0;
        else               g_deg_out[idx - GG * NN] = 0;
    }
    if (blockIdx.x == 0 && threadIdx.x == 0) {
        float m = alphas[0];
        for (int g = 1; g < GG; g++) m = fmaxf(m, alphas[g]);
        float s = 0.f, e[GG];
        for (int g = 0; g < GG; g++) { e[g] = expf(alphas[g] - m); s += e[g]; }
        for (int g = 0; g < GG; g++) g_alpha[g] = e[g] / s;
    }
}

__global__ void hist_kernel(const int* __restrict__ e0, const int* __restrict__ e1,
                            const int* __restrict__ e2) {
    int i = blockIdx.x * blockDim.x + threadIdx.x;
    if (i >= GG * EE) return;
    int g = i / EE, idx = i - g * EE;
    const int* e = (g == 0) ? e0 : (g == 1) ? e1 : e2;
    atomicAdd(&g_deg_out[g * NN + e[idx]], 1);
    atomicAdd(&g_deg_in [g * NN + e[EE + idx]], 1);
}

__global__ void scan_kernel() {
    int g = blockIdx.x;
    const int* cnt = g_deg_in + g * NN;
    int* off = g_off + g * (NN + 1);
    int* cur = g_cursor + g * NN;
    __shared__ int sh[1024];
    int carry = 0;
    for (int base = 0; base < NN; base += 1024) {
        int i = base + threadIdx.x;
        int v = (i < NN) ? cnt[i] : 0;
        sh[threadIdx.x] = v;
        __syncthreads();
        #pragma unroll
        for (int s = 1; s < 1024; s <<= 1) {
            int t = (threadIdx.x >= s) ? sh[threadIdx.x - s] : 0;
            __syncthreads();
            sh[threadIdx.x] += t;
            __syncthreads();
        }
        int incl = sh[threadIdx.x];
        if (i < NN) { off[i] = carry + incl - v; cur[i] = carry + incl - v; }
        carry += sh[1023];
        __syncthreads();
    }
    if (threadIdx.x == 0) off[NN] = carry;
}

__global__ void fill_kernel(const int* __restrict__ e0, const int* __restrict__ e1,
                            const int* __restrict__ e2) {
    int i = blockIdx.x * blockDim.x + threadIdx.x;
    if (i >= GG * EE) return;
    int g = i / EE, idx = i - g * EE;
    const int* e = (g == 0) ? e0 : (g == 1) ? e1 : e2;
    int src = e[idx];
    int dst = e[EE + idx];
    int p = atomicAdd(&g_cursor[g * NN + dst], 1);
    g_csr_src[g * EE + p] = src;
}

// ============================================================================
// fp32 -> bf16 hi/lo split conversions
// ============================================================================
__device__ __forceinline__ void split_bf16(float v, __nv_bfloat16& hi, __nv_bfloat16& lo) {
    hi = __float2bfloat16(v);
    lo = __float2bfloat16(v - __bfloat162float(hi));
}

__global__ void conv_x_kernel(const float* __restrict__ x) {
    int i = blockIdx.x * blockDim.x + threadIdx.x;
    int total = NN * IND;
    for (int idx = i; idx < total; idx += gridDim.x * blockDim.x) {
        __nv_bfloat16 h, l;
        split_bf16(x[idx], h, l);
        g_Xhi[idx] = h; g_Xlo[idx] = l;
    }
}

__global__ void conv_w_kernel(const float* __restrict__ W0, const float* __restrict__ W1,
                              const float* __restrict__ W2) {
    int i = blockIdx.x * blockDim.x + threadIdx.x;
    int total = GG * IND * HIDD;
    for (int idx = i; idx < total; idx += gridDim.x * blockDim.x) {
        int g = idx >> 18;
        int r = idx & 262143;
        int k = r >> 9;
        int n = r & 511;
        const float* W = (g == 0) ? W0 : (g == 1) ? W1 : W2;
        __nv_bfloat16 h, l;
        split_bf16(W[k * HIDD + n], h, l);
        size_t o = (size_t)(g * HIDD + n) * IND + k;
        g_Bthi[o] = h; g_Btlo[o] = l;
    }
}

__global__ void conv_wlin_kernel(const float* __restrict__ WL) {
    int i = blockIdx.x * blockDim.x + threadIdx.x;
    int total = CONCAT * OUTD;
    for (int idx = i; idx < total; idx += gridDim.x * blockDim.x) {
        int k = idx >> 8;
        int n = idx & 255;
        __nv_bfloat16 h, l;
        split_bf16(WL[idx], h, l);
        size_t o = (size_t)n * CONCAT + k;
        g_BtLhi[o] = h; g_BtLlo[o] = l;
    }
}

// ============================================================================
// bf16x3 GEMM via mma.sync. CTA tile 128x128, BK=64, 256 threads (8 warps,
// 2x4, warp tile 64x32), cp.async double-buffered SMEM, swizzled ldmatrix.
// mode 1: A=g_Xhi/lo (K=512),  B=g_Bthi/lo,   C=g_Y (ldc=1536), *rsqrt(deg_out)
// mode 2: A=g_Hhi/lo (K=1536), B=g_BtLhi/lo,  C=outp (ldc=256), +bias
// SMEM buffer layout (per 64KB buffer): Ahi@0, Alo@16K, Bhi@32K, Blo@48K,
// each tile 128 rows x 128 bytes, swizzled: off = row*128+col; off ^= (row&7)<<4
// ============================================================================
#define BUF_BYTES 65536
#define GSMEM_TOTAL (1024 + 2 * BUF_BYTES)

__device__ __forceinline__ void prefetch_chunk(uint32_t sdst,
        const __nv_bfloat16* __restrict__ Ahi, const __nv_bfloat16* __restrict__ Alo,
        const __nv_bfloat16* __restrict__ Bhi, const __nv_bfloat16* __restrict__ Blo,
        int kc, int m0, int n0, int K, int tid) {
    int row = tid >> 1;
    int cb = (tid & 1) * 4;
    int mrow = m0 + row; if (mrow >= NN) mrow = NN - 1;   // clamped rows never stored
    int nrow = n0 + row;
    const char* pAh = (const char*)(Ahi + (size_t)mrow * K) + kc * 128;
    const char* pAl = (const char*)(Alo + (size_t)mrow * K) + kc * 128;
    const char* pBh = (const char*)(Bhi + (size_t)nrow * K) + kc * 128;
    const char* pBl = (const char*)(Blo + (size_t)nrow * K) + kc * 128;
    #pragma unroll
    for (int q = 0; q < 4; q++) {
        int col = (cb + q) * 16;
        uint32_t swz = ((uint32_t)(row * 128 + col)) ^ ((uint32_t)(row & 7) << 4);
        CP16(sdst + swz,                 pAh + col);
        CP16(sdst + 16384 + swz,         pAl + col);
        CP16(sdst + 32768 + swz,         pBh + col);
        CP16(sdst + 49152 + swz,         pBl + col);
    }
}

__global__ void __launch_bounds__(256, 1)
mma_gemm_kernel(float* outp, const float* __restrict__ bias, int mode, int K) {
    extern __shared__ char smem_raw[];
    uint32_t sb0 = smem_to_u32(smem_raw);
    uint32_t sb = (sb0 + 1023) & ~1023u;

    const __nv_bfloat16 *Ahi, *Alo, *Bhi, *Blo;
    if (mode == 1) { Ahi = g_Xhi; Alo = g_Xlo; Bhi = g_Bthi;  Blo = g_Btlo;  }
    else           { Ahi = g_Hhi; Alo = g_Hlo; Bhi = g_BtLhi; Blo = g_BtLlo; }

    int tid = threadIdx.x;
    int lane = tid & 31, wid = tid >> 5;
    int warpM = wid >> 2, warpN = wid & 3;
    int n0 = blockIdx.x * 128;
    int m0 = blockIdx.y * 128;

    float acc[4][4][4];
    #pragma unroll
    for (int i = 0; i < 4; i++)
        #pragma unroll
        for (int j = 0; j < 4; j++)
            #pragma unroll
            for (int r = 0; r < 4; r++) acc[i][j][r] = 0.f;

    // static per-lane fragment address components
    int aRow = warpM * 64 + (lane & 15);            // + mi*16
    int aCol = (lane >> 4) * 16;                    // + q*32
    int bRow = warpN * 32 + (lane & 7) + (lane >> 4) * 8;  // + g*16
    int bCol = ((lane >> 3) & 1) * 16;              // + q*32

    int nk = K >> 6;
    prefetch_chunk(sb, Ahi, Alo, Bhi, Blo, 0, m0, n0, K, tid);
    CP_COMMIT();

    int buf = 0;
    for (int kc = 0; kc < nk; kc++) {
        if (kc + 1 < nk) {
            prefetch_chunk(sb + (buf ^ 1) * BUF_BYTES, Ahi, Alo, Bhi, Blo,
                           kc + 1, m0, n0, K, tid);
            CP_COMMIT();
            CP_WAIT(1);
        } else {
            CP_WAIT(0);
        }
        __syncthreads();

        uint32_t abase = sb + buf * BUF_BYTES;
        uint32_t lbase = abase + 16384;
        uint32_t bbase = abase + 32768;
        uint32_t cbase = abase + 49152;

        #pragma unroll
        for (int q = 0; q < 4; q++) {
            uint32_t ah[4][4], al[4][4], bh[2][4], bl[2][4];
            #pragma unroll
            for (int mi = 0; mi < 4; mi++) {
                int r = aRow + mi * 16;
                uint32_t off = ((uint32_t)(r * 128 + q * 32 + aCol)) ^ ((uint32_t)(r & 7) << 4);
                LDSM_X4(ah[mi][0], ah[mi][1], ah[mi][2], ah[mi][3], abase + off);
                LDSM_X4(al[mi][0], al[mi][1], al[mi][2], al[mi][3], lbase + off);
            }
            #pragma unroll
            for (int g = 0; g < 2; g++) {
                int r = bRow + g * 16;
                uint32_t off = ((uint32_t)(r * 128 + q * 32 + bCol)) ^ ((uint32_t)(r & 7) << 4);
                LDSM_X4(bh[g][0], bh[g][1], bh[g][2], bh[g][3], bbase + off);
                LDSM_X4(bl[g][0], bl[g][1], bl[g][2], bl[g][3], cbase + off);
            }
            #pragma unroll
            for (int mi = 0; mi < 4; mi++) {
                #pragma unroll
                for (int nj = 0; nj < 4; nj++) {
                    uint32_t bfh[2] = { bh[nj >> 1][(nj & 1) * 2], bh[nj >> 1][(nj & 1) * 2 + 1] };
                    uint32_t bfl[2] = { bl[nj >> 1][(nj & 1) * 2], bl[nj >> 1][(nj & 1) * 2 + 1] };
                    MMA_BF16(acc[mi][nj], ah[mi], bfh);   // Ah*Bh
                    MMA_BF16(acc[mi][nj], ah[mi], bfl);   // Ah*Bl
                    MMA_BF16(acc[mi][nj], al[mi], bfh);   // Al*Bh
                }
            }
        }
        __syncthreads();
        buf ^= 1;
    }

    // Epilogue: c0,c1 -> (row = lane/4, col = 2*(lane%3)..), c2,c3 -> row+8
    #pragma unroll
    for (int mi = 0; mi < 4; mi++) {
        #pragma unroll
        for (int nj = 0; nj < 4; nj++) {
            int m = m0 + warpM * 64 + mi * 16 + (lane >> 2);
            int n = n0 + warpN * 32 + nj * 8 + (lane & 3) * 2;
            float c0 = acc[mi][nj][0], c1 = acc[mi][nj][1];
            float c2 = acc[mi][nj][2], c3 = acc[mi][nj][3];
            if (mode == 1) {
                int g = n >> 9;
                if (m < NN) {
                    int d = g_deg_out[g * NN + m];
                    float s = rsqrtf((float)(d > 1 ? d : 1));
                    *(float2*)(g_Y + (size_t)m * CONCAT + n) = make_float2(c0 * s, c1 * s);
                }
                int m2 = m + 8;
                if (m2 < NN) {
                    int d = g_deg_out[g * NN + m2];
                    float s = rsqrtf((float)(d > 1 ? d : 1));
                    *(float2*)(g_Y + (size_t)m2 * CONCAT + n) = make_float2(c2 * s, c3 * s);
                }
            } else {
                float bx = bias[n], by = bias[n + 1];
                if (m < NN)
                    *(float2*)(outp + (size_t)m * OUTD + n) = make_float2(c0 + bx, c1 + by);
                if (m + 8 < NN)
                    *(float2*)(outp + (size_t)(m + 8) * OUTD + n) = make_float2(c2 + bx, c3 + by);
            }
        }
    }
}

// ============================================================================
// CSR aggregation + rsqrt(deg_in) + bias + alpha + tanh -> bf16 hi/lo H
// ============================================================================
__global__ void __launch_bounds__(128)
agg_kernel(const float* __restrict__ b0, const float* __restrict__ b1,
           const float* __restrict__ b2) {
    int dst = blockIdx.x;
    int g = blockIdx.y;
    int c = threadIdx.x * 4;

    int beg = g_off[g * (NN + 1) + dst];
    int end = g_off[g * (NN + 1) + dst + 1];
    const int* srcs = g_csr_src + g * EE;
    const float* Ybase = g_Y + (size_t)g * HIDD + c;

    float4 acc = make_float4(0.f, 0.f, 0.f, 0.f);
    for (int e = beg; e < end; e++) {
        int s = srcs[e];
        float4 v = *(const float4*)(Ybase + (size_t)s * CONCAT);
        acc.x += v.x; acc.y += v.y; acc.z += v.z; acc.w += v.w;
    }

    int d = g_deg_in[g * NN + dst];
    float rsv = rsqrtf((float)(d > 1 ? d : 1));
    const float* bb = (g == 0) ? b0 : (g == 1) ? b1 : b2;
    float4 bv = *(const float4*)(bb + c);
    float a = g_alpha[g];

    float h[4];
    h[0] = tanhf(a * (acc.x * rsv + bv.x));
    h[1] = tanhf(a * (acc.y * rsv + bv.y));
    h[2] = tanhf(a * (acc.z * rsv + bv.z));
    h[3] = tanhf(a * (acc.w * rsv + bv.w));

    size_t base = (size_t)dst * CONCAT + (size_t)g * HIDD + c;
    __nv_bfloat16 hi[4], lo[4];
    #pragma unroll
    for (int j = 0; j < 4; j++) split_bf16(h[j], hi[j], lo[j]);
    *(__nv_bfloat162*)(g_Hhi + base)     = __halves2bfloat162(hi[0], hi[1]);
    *(__nv_bfloat162*)(g_Hhi + base + 2) = __halves2bfloat162(hi[2], hi[3]);
    *(__nv_bfloat162*)(g_Hlo + base)     = __halves2bfloat162(lo[0], lo[1]);
    *(__nv_bfloat162*)(g_Hlo + base + 2) = __halves2bfloat162(lo[2], lo[3]);
}

// ============================================================================
// Launch — inputs bound by element count (robust to metadata ordering)
// ============================================================================
extern "C" void kernel_launch(void* const* d_in, const int* in_sizes, int n_in,
                              void* d_out, int out_size) {
    const float* x = nullptr;
    const int*   e[GG]  = {nullptr, nullptr, nullptr};
    const float* W[GG]  = {nullptr, nullptr, nullptr};
    const float* b[GG]  = {nullptr, nullptr, nullptr};
    const float* alphas = nullptr;
    const float* W_lin  = nullptr;
    const float* b_lin  = nullptr;
    int ne = 0, nw = 0, nb = 0;

    for (int i = 0; i < n_in; i++) {
        int sz = in_sizes[i];
        if      (sz == NN * IND)      x = (const float*)d_in[i];
        else if (sz == 2 * EE)        { if (ne < GG) e[ne++] = (const int*)d_in[i]; }
        else if (sz == IND * HIDD)    { if (nw < GG) W[nw++] = (const float*)d_in[i]; }
        else if (sz == HIDD)          { if (nb < GG) b[nb++] = (const float*)d_in[i]; }
        else if (sz == GG)            alphas = (const float*)d_in[i];
        else if (sz == CONCAT * OUTD) W_lin = (const float*)d_in[i];
        else if (sz == OUTD)          b_lin = (const float*)d_in[i];
    }
    float* out = (float*)d_out;

    cudaFuncSetAttribute(mma_gemm_kernel, cudaFuncAttributeMaxDynamicSharedMemorySize,
                         GSMEM_TOTAL);

    zero_kernel<<<256, 256>>>(alphas);
    conv_x_kernel<<<2048, 256>>>(x);
    conv_w_kernel<<<1024, 256>>>(W[0], W[1], W[2]);
    conv_wlin_kernel<<<512, 256>>>(W_lin);
    hist_kernel<<<(GG * EE + 255) / 256, 256>>>(e[0], e[1], e[2]);
    scan_kernel<<<GG, 1024>>>();
    fill_kernel<<<(GG * EE + 255) / 256, 256>>>(e[0], e[1], e[2]);

    int mtiles = (NN + 127) / 128;   // 235
    // GEMM1 (3 branches fused along N): [30000x512] @ Bt[1536x512]^T -> g_Y
    dim3 grid1(CONCAT / 128, mtiles);
    mma_gemm_kernel<<<grid1, 256, GSMEM_TOTAL>>>(nullptr, nullptr, 1, IND);

    // aggregation + epilogue -> Hhi/Hlo
    dim3 gridA(NN, GG);
    agg_kernel<<<gridA, 128>>>(b[0], b[1], b[2]);

    // GEMM2: [30000x1536] @ BtL[256x1536]^T + b_lin -> out
    dim3 grid2(OUTD / 128, mtiles);
    mma_gemm_kernel<<<grid2, 256, GSMEM_TOTAL>>>(out, b_lin, 2, CONCAT);
}